// round 6
// baseline (speedup 1.0000x reference)
#include <cuda_runtime.h>

#define TT 256

// Ping-pong scratch (static device arrays: no allocation anywhere).
__device__ float g_bufX[33554432];
__device__ float g_bufY[33554432];

__device__ __forceinline__ void ffma2(unsigned long long& acc,
                                      unsigned long long w,
                                      unsigned long long v) {
    asm("fma.rn.f32x2 %0, %1, %2, %0;" : "+l"(acc) : "l"(w), "l"(v));
}

// ---------------------------------------------------------------------------
// Standalone dynamics kernel (only for input-psp, pool, upsample layers).
// MODE 0: psp only
// MODE 2: sumpool2 + spike + psp (4-tap gather fused)
// MODE 3: bilinear-up2 + spike + psp (4-tap gather fused)
// Software-pipelined register prefetch (double-buffered chunks).
// ---------------------------------------------------------------------------
template<int MODE>
__global__ void dyn_kernel(const float* __restrict__ in, float* __restrict__ out,
                           int H, int W, int N)
{
    int n = blockIdx.x * blockDim.x + threadIdx.x;
    if (n >= N) return;

    const float dsr  = 0.9048374180359595f;   // exp(-1/10)
    const float psc  = 0.27182818284590452f;  // e/10
    const float dref = 0.36787944117144233f;  // exp(-1)

    constexpr int S  = (MODE == 2 || MODE == 3) ? 4 : 1;
    constexpr int CH = (S == 4) ? 8 : 16;
    constexpr int F4 = CH / 4;
    constexpr int NC = TT / CH;

    const float* p[S];
    float w00 = 0.f, w01 = 0.f, w10 = 0.f, w11 = 0.f;

    if (MODE == 2) {
        int x = n % W, y = (n / W) % H, bc = n / (W * H);
        int Win = 2 * W;
        const float* base = in + (((long)bc * (2 * H) + 2 * y) * Win + 2 * x) * TT;
        p[0] = base;
        p[1] = base + TT;
        p[2] = base + (long)Win * TT;
        p[3] = base + (long)(Win + 1) * TT;
    } else if (MODE == 3) {
        int x = n % W, y = (n / W) % H, bc = n / (W * H);
        int Hin = H / 2, Win = W / 2;
        int jy = y >> 1, jx = x >> 1;
        int ya, yb, xa, xb; float wya, wyb, wxa, wxb;
        if ((y & 1) == 0) { ya = (jy > 0) ? jy - 1 : 0; yb = jy; wya = 0.25f; wyb = 0.75f; }
        else              { ya = jy; yb = (jy + 1 < Hin) ? jy + 1 : Hin - 1; wya = 0.75f; wyb = 0.25f; }
        if ((x & 1) == 0) { xa = (jx > 0) ? jx - 1 : 0; xb = jx; wxa = 0.25f; wxb = 0.75f; }
        else              { xa = jx; xb = (jx + 1 < Win) ? jx + 1 : Win - 1; wxa = 0.75f; wxb = 0.25f; }
        const float* base = in + (long)bc * Hin * Win * TT;
        p[0] = base + ((long)ya * Win + xa) * TT; w00 = wya * wxa;
        p[1] = base + ((long)ya * Win + xb) * TT; w01 = wya * wxb;
        p[2] = base + ((long)yb * Win + xa) * TT; w10 = wyb * wxa;
        p[3] = base + ((long)yb * Win + xb) * TT; w11 = wyb * wxb;
    } else {
        p[0] = in + (long)n * TT;
    }

    float* ob = out + (long)n * TT;

    float4 buf[2][S][F4];
    #pragma unroll
    for (int s = 0; s < S; s++)
        #pragma unroll
        for (int f = 0; f < F4; f++)
            buf[0][s][f] = *(const float4*)(p[s] + f * 4);

    float g1 = 0.f, g2 = 0.f, r = 0.f;

    for (int c = 0; c < NC; c++) {
        int cur = c & 1, nxt = cur ^ 1;
        if (c + 1 < NC) {
            #pragma unroll
            for (int s = 0; s < S; s++)
                #pragma unroll
                for (int f = 0; f < F4; f++)
                    buf[nxt][s][f] = *(const float4*)(p[s] + (c + 1) * CH + f * 4);
        }
        #pragma unroll
        for (int f = 0; f < F4; f++) {
            float u[4];
            if (MODE == 2) {
                float4 a = buf[cur][0][f], b = buf[cur][1][f];
                float4 cc = buf[cur][2][f], d = buf[cur][3][f];
                u[0] = 2.75f * ((a.x + b.x) + (cc.x + d.x));
                u[1] = 2.75f * ((a.y + b.y) + (cc.y + d.y));
                u[2] = 2.75f * ((a.z + b.z) + (cc.z + d.z));
                u[3] = 2.75f * ((a.w + b.w) + (cc.w + d.w));
            } else if (MODE == 3) {
                float4 a = buf[cur][0][f], b = buf[cur][1][f];
                float4 cc = buf[cur][2][f], d = buf[cur][3][f];
                u[0] = w00 * a.x + w01 * b.x + w10 * cc.x + w11 * d.x;
                u[1] = w00 * a.y + w01 * b.y + w10 * cc.y + w11 * d.y;
                u[2] = w00 * a.z + w01 * b.z + w10 * cc.z + w11 * d.z;
                u[3] = w00 * a.w + w01 * b.w + w10 * cc.w + w11 * d.w;
            } else {
                float4 a = buf[cur][0][f];
                u[0] = a.x; u[1] = a.y; u[2] = a.z; u[3] = a.w;
            }
            float o[4];
            #pragma unroll
            for (int j = 0; j < 4; j++) {
                if (MODE == 0) {
                    g1 = fmaf(dsr, g1, u[j]);
                    g2 = fmaf(dsr, g2, g1);
                    o[j] = psc * (g2 - g1);
                } else {
                    float v = u[j] + r - 10.0f;
                    float s = (v >= 0.f) ? 1.f : 0.f;
                    r = dref * (r - 20.f * s);
                    g1 = fmaf(dsr, g1, s);
                    g2 = fmaf(dsr, g2, g1);
                    o[j] = psc * (g2 - g1);
                }
            }
            *(float4*)(ob + c * CH + f * 4) = make_float4(o[0], o[1], o[2], o[3]);
        }
    }
}

// ---------------------------------------------------------------------------
// Fused conv + spike/psp epilogue.
// One output pixel per block, OCG output channels, 128 threads x 2 timesteps,
// packed fp32x2 FMA (tied "+l" operand -> clean FFMA2, no MOV churn).
// After the conv, accumulators are staged in smem; OCG threads run the
// 256-step spike(+psp) recurrence in place; all threads store the next
// layer's PSP tensor coalesced. The raw conv activation never hits GMEM.
// EPI = 1: spike + psp.  EPI = 4: spike only (final layer).
// ---------------------------------------------------------------------------
template<int IC, int KS, int PAD, int OCG, int EPI>
__global__ __launch_bounds__(128)
void conv_kernel(const float* __restrict__ in, const float* __restrict__ wgt,
                 float* __restrict__ out, int H, int W, int OC)
{
    __shared__ __align__(16) unsigned long long sw[IC * KS * KS * OCG];
    __shared__ __align__(16) float sa[OCG][260];

    int pix = blockIdx.x;
    int x = pix % W, y = (pix / W) % H, b = pix / (W * H);
    int oc0 = blockIdx.y * OCG;

    for (int i = threadIdx.x; i < IC * KS * KS * OCG; i += 128) {
        int k = i / OCG, o = i % OCG;
        unsigned u = __float_as_uint(wgt[(long)(oc0 + o) * IC * KS * KS + k]);
        sw[i] = ((unsigned long long)u << 32) | u;
    }
    __syncthreads();

    int t = threadIdx.x * 2;
    unsigned long long acc[OCG];
    #pragma unroll
    for (int o = 0; o < OCG; o++) acc[o] = 0ull;

    const long planeT = (long)H * W * TT;
    const float* inb = in + (long)b * IC * planeT + t;

    #pragma unroll
    for (int kh = 0; kh < KS; kh++) {
        int yy = y + kh - PAD;
        if (yy < 0 || yy >= H) continue;
        #pragma unroll
        for (int kw = 0; kw < KS; kw++) {
            int xx = x + kw - PAD;
            if (xx < 0 || xx >= W) continue;
            const float* p = inb + ((long)yy * W + xx) * TT;
            int kidx = kh * KS + kw;
            #pragma unroll 4
            for (int ic = 0; ic < IC; ic++) {
                unsigned long long v = *(const unsigned long long*)(p + (long)ic * planeT);
                const unsigned long long* swp = &sw[(ic * KS * KS + kidx) * OCG];
                if constexpr (OCG % 2 == 0) {
                    #pragma unroll
                    for (int o = 0; o < OCG; o += 2) {
                        ulonglong2 wv = *(const ulonglong2*)(swp + o);
                        ffma2(acc[o    ], wv.x, v);
                        ffma2(acc[o + 1], wv.y, v);
                    }
                } else {
                    #pragma unroll
                    for (int o = 0; o < OCG; o++)
                        ffma2(acc[o], swp[o], v);
                }
            }
        }
    }

    // Stage conv results: sa[oc][t] (pad 260 avoids systematic conflicts).
    #pragma unroll
    for (int o = 0; o < OCG; o++)
        *(float2*)&sa[o][t] = *(float2*)&acc[o];
    __syncthreads();

    // Per-channel serial recurrence over T (OCG threads; hidden under the
    // conv work of co-resident blocks).
    if (threadIdx.x < OCG) {
        const float dsr  = 0.9048374180359595f;
        const float psc  = 0.27182818284590452f;
        const float dref = 0.36787944117144233f;
        int oc = threadIdx.x;
        float g1 = 0.f, g2 = 0.f, r = 0.f;
        float4 nxt = *(float4*)&sa[oc][0];
        for (int tt = 0; tt < TT; tt += 4) {
            float4 a = nxt;
            if (tt + 4 < TT) nxt = *(float4*)&sa[oc][tt + 4];
            float u[4] = {a.x, a.y, a.z, a.w};
            float o4[4];
            #pragma unroll
            for (int j = 0; j < 4; j++) {
                float v = u[j] + r - 10.0f;
                float s = (v >= 0.f) ? 1.f : 0.f;
                r = dref * (r - 20.f * s);
                if (EPI == 4) {
                    o4[j] = s;
                } else {
                    g1 = fmaf(dsr, g1, s);
                    g2 = fmaf(dsr, g2, g1);
                    o4[j] = psc * (g2 - g1);
                }
            }
            *(float4*)&sa[oc][tt] = make_float4(o4[0], o4[1], o4[2], o4[3]);
        }
    }
    __syncthreads();

    // Coalesced store of the PSP (or spike) tensor.
    float* ob = out + ((long)b * OC + oc0) * planeT + ((long)y * W + x) * TT + t;
    #pragma unroll
    for (int o = 0; o < OCG; o++)
        *(float2*)(ob + (long)o * planeT) = *(float2*)&sa[o][t];
}

// ---------------------------------------------------------------------------
// 10 launches, ping-pong X<->Y:
//   P0=psp(in)->X; P1=conv1+sp(X)->Y; P2=pool_sp(Y)->X; P3=conv2+sp(X)->Y;
//   P4=pool_sp(Y)->X; P5=conv3+sp(X)->Y; P6=up_sp(Y)->X; P7=conv4+sp(X)->Y;
//   P8=up_sp(Y)->X; out=conv_out+spike(X)
// ---------------------------------------------------------------------------
extern "C" void kernel_launch(void* const* d_in, const int* in_sizes, int n_in,
                              void* d_out, int out_size)
{
    const float* inp = (const float*)d_in[0];  // [4,1,32,32,256]
    const float* w1  = (const float*)d_in[1];  // [16,1,5,5,1]
    const float* w2  = (const float*)d_in[2];  // [32,16,3,3,1]
    const float* w3  = (const float*)d_in[3];  // [64,32,3,3,1]
    const float* w4  = (const float*)d_in[4];  // [32,64,3,3,1]
    const float* wo  = (const float*)d_in[5];  // [1,32,1,1,1]
    float* out = (float*)d_out;

    float *X, *Y;
    cudaGetSymbolAddress((void**)&X, g_bufX);
    cudaGetSymbolAddress((void**)&Y, g_bufY);

    // P0 = psp(input) -> X        (N=4096: 32-thread blocks -> 128 blocks)
    dyn_kernel<0><<<128, 32>>>(inp, X, 32, 32, 4096);

    // P1 = spike/psp(conv1(P0)) -> Y
    conv_kernel<1, 5, 2, 16, 1><<<dim3(4096, 1), 128>>>(X, w1, Y, 32, 32, 16);

    // P2 = pool+spike+psp(P1) -> X   [4,16,16,16]  (N=16384: 256 blocks)
    dyn_kernel<2><<<256, 64>>>(Y, X, 16, 16, 16384);

    // P3 = spike/psp(conv2(P2)) -> Y
    conv_kernel<16, 3, 1, 16, 1><<<dim3(1024, 2), 128>>>(X, w2, Y, 16, 16, 32);

    // P4 = pool+spike+psp(P3) -> X   [4,32,8,8]  (N=8192: 256 blocks)
    dyn_kernel<2><<<256, 32>>>(Y, X, 8, 8, 8192);

    // P5 = spike/psp(conv3(P4)) -> Y
    conv_kernel<32, 3, 1, 16, 1><<<dim3(256, 4), 128>>>(X, w3, Y, 8, 8, 64);

    // P6 = up+spike+psp(P5) -> X   [4,64,16,16]  (N=65536)
    dyn_kernel<3><<<512, 128>>>(Y, X, 16, 16, 65536);

    // P7 = spike/psp(conv4(P6)) -> Y   (OCG=8 keeps smem under 48KB)
    conv_kernel<64, 3, 1, 8, 1><<<dim3(1024, 4), 128>>>(X, w4, Y, 16, 16, 32);

    // P8 = up+spike+psp(P7) -> X   [4,32,32,32]  (N=131072)
    dyn_kernel<3><<<1024, 128>>>(Y, X, 32, 32, 131072);

    // out = spike(conv_out(P8))
    conv_kernel<32, 1, 0, 1, 4><<<dim3(4096, 1), 128>>>(X, wo, out, 32, 32, 1);
}

// round 7
// speedup vs baseline: 1.0019x; 1.0019x over previous
#include <cuda_runtime.h>

#define TT 256

// Ping-pong scratch (static device arrays: no allocation anywhere).
__device__ float g_bufX[33554432];
__device__ float g_bufY[33554432];

__device__ __forceinline__ void ffma2(unsigned long long& acc,
                                      unsigned long long w,
                                      unsigned long long v) {
    asm("fma.rn.f32x2 %0, %1, %2, %0;" : "+l"(acc) : "l"(w), "l"(v));
}

// ---------------------------------------------------------------------------
// Standalone dynamics kernel (input-psp, pool, upsample layers).
// MODE 0: psp only
// MODE 2: sumpool2 + spike + psp (4-tap gather fused)
// MODE 3: bilinear-up2 + spike + psp (4-tap gather fused)
// TRUE double-buffered register prefetch: two NAMED buffers, loop unrolled x2
// so all buffer indices are compile-time (no local-memory fallback).
// ---------------------------------------------------------------------------
template<int MODE>
__global__ void dyn_kernel(const float* __restrict__ in, float* __restrict__ out,
                           int H, int W, int N)
{
    int n = blockIdx.x * blockDim.x + threadIdx.x;
    if (n >= N) return;

    const float dsr  = 0.9048374180359595f;   // exp(-1/10)
    const float psc  = 0.27182818284590452f;  // e/10
    const float dref = 0.36787944117144233f;  // exp(-1)

    constexpr int S  = (MODE == 2 || MODE == 3) ? 4 : 1;
    constexpr int CH = (S == 4) ? 8 : 16;
    constexpr int F4 = CH / 4;
    constexpr int NC = TT / CH;              // 32 or 16 (even)

    const float* p[S];
    float w00 = 0.f, w01 = 0.f, w10 = 0.f, w11 = 0.f;

    if (MODE == 2) {
        int x = n % W, y = (n / W) % H, bc = n / (W * H);
        int Win = 2 * W;
        const float* base = in + (((long)bc * (2 * H) + 2 * y) * Win + 2 * x) * TT;
        p[0] = base;
        p[1] = base + TT;
        p[2] = base + (long)Win * TT;
        p[3] = base + (long)(Win + 1) * TT;
    } else if (MODE == 3) {
        int x = n % W, y = (n / W) % H, bc = n / (W * H);
        int Hin = H / 2, Win = W / 2;
        int jy = y >> 1, jx = x >> 1;
        int ya, yb, xa, xb; float wya, wyb, wxa, wxb;
        if ((y & 1) == 0) { ya = (jy > 0) ? jy - 1 : 0; yb = jy; wya = 0.25f; wyb = 0.75f; }
        else              { ya = jy; yb = (jy + 1 < Hin) ? jy + 1 : Hin - 1; wya = 0.75f; wyb = 0.25f; }
        if ((x & 1) == 0) { xa = (jx > 0) ? jx - 1 : 0; xb = jx; wxa = 0.25f; wxb = 0.75f; }
        else              { xa = jx; xb = (jx + 1 < Win) ? jx + 1 : Win - 1; wxa = 0.75f; wxb = 0.25f; }
        const float* base = in + (long)bc * Hin * Win * TT;
        p[0] = base + ((long)ya * Win + xa) * TT; w00 = wya * wxa;
        p[1] = base + ((long)ya * Win + xb) * TT; w01 = wya * wxb;
        p[2] = base + ((long)yb * Win + xa) * TT; w10 = wyb * wxa;
        p[3] = base + ((long)yb * Win + xb) * TT; w11 = wyb * wxb;
    } else {
        p[0] = in + (long)n * TT;
    }

    float* ob = out + (long)n * TT;

    float g1 = 0.f, g2 = 0.f, r = 0.f;

    float4 A[S][F4], B[S][F4];

    auto load = [&](float4 (&buf)[S][F4], int c) {
        #pragma unroll
        for (int s = 0; s < S; s++)
            #pragma unroll
            for (int f = 0; f < F4; f++)
                buf[s][f] = *(const float4*)(p[s] + c * CH + f * 4);
    };

    auto compute = [&](float4 (&buf)[S][F4], int c) {
        #pragma unroll
        for (int f = 0; f < F4; f++) {
            float u[4];
            if (MODE == 2) {
                float4 a = buf[0][f], b = buf[1][f], cc = buf[2][f], d = buf[3][f];
                u[0] = 2.75f * ((a.x + b.x) + (cc.x + d.x));
                u[1] = 2.75f * ((a.y + b.y) + (cc.y + d.y));
                u[2] = 2.75f * ((a.z + b.z) + (cc.z + d.z));
                u[3] = 2.75f * ((a.w + b.w) + (cc.w + d.w));
            } else if (MODE == 3) {
                float4 a = buf[0][f], b = buf[1][f], cc = buf[2][f], d = buf[3][f];
                u[0] = w00 * a.x + w01 * b.x + w10 * cc.x + w11 * d.x;
                u[1] = w00 * a.y + w01 * b.y + w10 * cc.y + w11 * d.y;
                u[2] = w00 * a.z + w01 * b.z + w10 * cc.z + w11 * d.z;
                u[3] = w00 * a.w + w01 * b.w + w10 * cc.w + w11 * d.w;
            } else {
                float4 a = buf[0][f];
                u[0] = a.x; u[1] = a.y; u[2] = a.z; u[3] = a.w;
            }
            float o[4];
            #pragma unroll
            for (int j = 0; j < 4; j++) {
                if (MODE == 0) {
                    g1 = fmaf(dsr, g1, u[j]);
                    g2 = fmaf(dsr, g2, g1);
                    o[j] = psc * (g2 - g1);
                } else {
                    float v = u[j] + r - 10.0f;
                    float s = (v >= 0.f) ? 1.f : 0.f;
                    r = dref * (r - 20.f * s);
                    g1 = fmaf(dsr, g1, s);
                    g2 = fmaf(dsr, g2, g1);
                    o[j] = psc * (g2 - g1);
                }
            }
            *(float4*)(ob + c * CH + f * 4) = make_float4(o[0], o[1], o[2], o[3]);
        }
    };

    load(A, 0);
    for (int c = 0; c < NC; c += 2) {
        load(B, c + 1);                 // prefetch chunk c+1 into B
        compute(A, c);                  // serial recurrence on chunk c
        if (c + 2 < NC) load(A, c + 2); // prefetch chunk c+2 into A
        compute(B, c + 1);
    }
}

// ---------------------------------------------------------------------------
// Fused conv + spike/psp epilogue. 64 threads = one output pixel; each thread
// owns 4 timesteps (float4 data = 2 packed u64), OCG output channels.
// Inner tap: 1 LDG.128 + OCG/2 LDS.128 (pre-duplicated weight pairs) +
// 2*OCG fma.rn.f32x2  -> LDS traffic per FFMA2 is half of the R5 kernel.
// EPI = 1: spike + psp.  EPI = 4: spike only (final layer).
// ---------------------------------------------------------------------------
template<int IC, int KS, int PAD, int OCG, int EPI>
__global__ __launch_bounds__(64)
void conv_kernel(const float* __restrict__ in, const float* __restrict__ wgt,
                 float* __restrict__ out, int H, int W, int OC)
{
    __shared__ __align__(16) unsigned long long sw[IC * KS * KS * OCG];
    __shared__ __align__(16) float sa[OCG][260];

    int pix = blockIdx.x;
    int x = pix % W, y = (pix / W) % H, b = pix / (W * H);
    int oc0 = blockIdx.y * OCG;

    for (int i = threadIdx.x; i < IC * KS * KS * OCG; i += 64) {
        int k = i / OCG, o = i % OCG;
        unsigned u = __float_as_uint(wgt[(long)(oc0 + o) * IC * KS * KS + k]);
        sw[i] = ((unsigned long long)u << 32) | u;
    }
    __syncthreads();

    int t = threadIdx.x * 4;
    unsigned long long acc[OCG][2];
    #pragma unroll
    for (int o = 0; o < OCG; o++) { acc[o][0] = 0ull; acc[o][1] = 0ull; }

    const long planeT = (long)H * W * TT;
    const float* inb = in + (long)b * IC * planeT + t;

    #pragma unroll
    for (int kh = 0; kh < KS; kh++) {
        int yy = y + kh - PAD;
        if (yy < 0 || yy >= H) continue;
        #pragma unroll
        for (int kw = 0; kw < KS; kw++) {
            int xx = x + kw - PAD;
            if (xx < 0 || xx >= W) continue;
            const float* p = inb + ((long)yy * W + xx) * TT;
            int kidx = kh * KS + kw;
            #pragma unroll 2
            for (int ic = 0; ic < IC; ic++) {
                ulonglong2 v = *(const ulonglong2*)(p + (long)ic * planeT);
                const unsigned long long* swp = &sw[(ic * KS * KS + kidx) * OCG];
                if constexpr (OCG % 2 == 0) {
                    #pragma unroll
                    for (int o = 0; o < OCG; o += 2) {
                        ulonglong2 wv = *(const ulonglong2*)(swp + o);
                        ffma2(acc[o    ][0], wv.x, v.x);
                        ffma2(acc[o    ][1], wv.x, v.y);
                        ffma2(acc[o + 1][0], wv.y, v.x);
                        ffma2(acc[o + 1][1], wv.y, v.y);
                    }
                } else {
                    #pragma unroll
                    for (int o = 0; o < OCG; o++) {
                        unsigned long long wv = swp[o];
                        ffma2(acc[o][0], wv, v.x);
                        ffma2(acc[o][1], wv, v.y);
                    }
                }
            }
        }
    }

    // Stage conv results in smem: sa[oc][t..t+3].
    #pragma unroll
    for (int o = 0; o < OCG; o++) {
        *(float2*)&sa[o][t]     = *(float2*)&acc[o][0];
        *(float2*)&sa[o][t + 2] = *(float2*)&acc[o][1];
    }
    __syncthreads();

    // Per-channel serial recurrence over T (OCG threads; hidden under the
    // conv mainloops of co-resident blocks).
    if (threadIdx.x < OCG) {
        const float dsr  = 0.9048374180359595f;
        const float psc  = 0.27182818284590452f;
        const float dref = 0.36787944117144233f;
        int oc = threadIdx.x;
        float g1 = 0.f, g2 = 0.f, r = 0.f;
        float4 nxt = *(float4*)&sa[oc][0];
        for (int tt = 0; tt < TT; tt += 4) {
            float4 a = nxt;
            if (tt + 4 < TT) nxt = *(float4*)&sa[oc][tt + 4];
            float u[4] = {a.x, a.y, a.z, a.w};
            float o4[4];
            #pragma unroll
            for (int j = 0; j < 4; j++) {
                float v = u[j] + r - 10.0f;
                float s = (v >= 0.f) ? 1.f : 0.f;
                r = dref * (r - 20.f * s);
                if (EPI == 4) {
                    o4[j] = s;
                } else {
                    g1 = fmaf(dsr, g1, s);
                    g2 = fmaf(dsr, g2, g1);
                    o4[j] = psc * (g2 - g1);
                }
            }
            *(float4*)&sa[oc][tt] = make_float4(o4[0], o4[1], o4[2], o4[3]);
        }
    }
    __syncthreads();

    // Coalesced float4 store of the PSP (or spike) tensor.
    float* ob = out + ((long)b * OC + oc0) * planeT + ((long)y * W + x) * TT + t;
    #pragma unroll
    for (int o = 0; o < OCG; o++)
        *(float4*)(ob + (long)o * planeT) = *(float4*)&sa[o][t];
}

// ---------------------------------------------------------------------------
// 10 launches, ping-pong X<->Y:
//   P0=psp(in)->X; P1=conv1+sp(X)->Y; P2=pool_sp(Y)->X; P3=conv2+sp(X)->Y;
//   P4=pool_sp(Y)->X; P5=conv3+sp(X)->Y; P6=up_sp(Y)->X; P7=conv4+sp(X)->Y;
//   P8=up_sp(Y)->X; out=conv_out+spike(X)
// ---------------------------------------------------------------------------
extern "C" void kernel_launch(void* const* d_in, const int* in_sizes, int n_in,
                              void* d_out, int out_size)
{
    const float* inp = (const float*)d_in[0];  // [4,1,32,32,256]
    const float* w1  = (const float*)d_in[1];  // [16,1,5,5,1]
    const float* w2  = (const float*)d_in[2];  // [32,16,3,3,1]
    const float* w3  = (const float*)d_in[3];  // [64,32,3,3,1]
    const float* w4  = (const float*)d_in[4];  // [32,64,3,3,1]
    const float* wo  = (const float*)d_in[5];  // [1,32,1,1,1]
    float* out = (float*)d_out;

    float *X, *Y;
    cudaGetSymbolAddress((void**)&X, g_bufX);
    cudaGetSymbolAddress((void**)&Y, g_bufY);

    // P0 = psp(input) -> X        (N=4096)
    dyn_kernel<0><<<128, 32>>>(inp, X, 32, 32, 4096);

    // P1 = spike/psp(conv1(P0)) -> Y
    conv_kernel<1, 5, 2, 16, 1><<<dim3(4096, 1), 64>>>(X, w1, Y, 32, 32, 16);

    // P2 = pool+spike+psp(P1) -> X   [4,16,16,16]  (N=16384)
    dyn_kernel<2><<<256, 64>>>(Y, X, 16, 16, 16384);

    // P3 = spike/psp(conv2(P2)) -> Y
    conv_kernel<16, 3, 1, 16, 1><<<dim3(1024, 2), 64>>>(X, w2, Y, 16, 16, 32);

    // P4 = pool+spike+psp(P3) -> X   [4,32,8,8]  (N=8192)
    dyn_kernel<2><<<256, 32>>>(Y, X, 8, 8, 8192);

    // P5 = spike/psp(conv3(P4)) -> Y
    conv_kernel<32, 3, 1, 16, 1><<<dim3(256, 4), 64>>>(X, w3, Y, 8, 8, 64);

    // P6 = up+spike+psp(P5) -> X   [4,64,16,16]  (N=65536)
    dyn_kernel<3><<<512, 128>>>(Y, X, 16, 16, 65536);

    // P7 = spike/psp(conv4(P6)) -> Y   (OCG=8 keeps smem bounded)
    conv_kernel<64, 3, 1, 8, 1><<<dim3(1024, 4), 64>>>(X, w4, Y, 16, 16, 32);

    // P8 = up+spike+psp(P7) -> X   [4,32,32,32]  (N=131072)
    dyn_kernel<3><<<1024, 128>>>(Y, X, 32, 32, 131072);

    // out = spike(conv_out(P8))
    conv_kernel<32, 1, 0, 1, 4><<<dim3(4096, 1), 64>>>(X, wo, out, 32, 32, 1);
}

// round 8
// speedup vs baseline: 1.1746x; 1.1723x over previous
#include <cuda_runtime.h>

#define TT 256

// Ping-pong scratch (static device arrays: no allocation anywhere).
__device__ float g_bufX[33554432];
__device__ float g_bufY[33554432];

__device__ __forceinline__ void ffma2(unsigned long long& acc,
                                      unsigned long long w,
                                      unsigned long long v) {
    asm("fma.rn.f32x2 %0, %1, %2, %0;" : "+l"(acc) : "l"(w), "l"(v));
}

// ---------------------------------------------------------------------------
// Standalone dynamics kernel (input-psp, pool, upsample layers).
// MODE 0: psp only
// MODE 2: sumpool2 + spike + psp (4-tap gather fused)
// MODE 3: bilinear-up2 + spike + psp (4-tap gather fused)
// Double-buffered register prefetch with NAMED buffers (compile-time indices).
// ---------------------------------------------------------------------------
template<int MODE>
__global__ void dyn_kernel(const float* __restrict__ in, float* __restrict__ out,
                           int H, int W, int N)
{
    int n = blockIdx.x * blockDim.x + threadIdx.x;
    if (n >= N) return;

    const float dsr  = 0.9048374180359595f;   // exp(-1/10)
    const float psc  = 0.27182818284590452f;  // e/10
    const float dref = 0.36787944117144233f;  // exp(-1)

    constexpr int S  = (MODE == 2 || MODE == 3) ? 4 : 1;
    constexpr int CH = (S == 4) ? 8 : 16;
    constexpr int F4 = CH / 4;
    constexpr int NC = TT / CH;              // even

    const float* p[S];
    float w00 = 0.f, w01 = 0.f, w10 = 0.f, w11 = 0.f;

    if (MODE == 2) {
        int x = n % W, y = (n / W) % H, bc = n / (W * H);
        int Win = 2 * W;
        const float* base = in + (((long)bc * (2 * H) + 2 * y) * Win + 2 * x) * TT;
        p[0] = base;
        p[1] = base + TT;
        p[2] = base + (long)Win * TT;
        p[3] = base + (long)(Win + 1) * TT;
    } else if (MODE == 3) {
        int x = n % W, y = (n / W) % H, bc = n / (W * H);
        int Hin = H / 2, Win = W / 2;
        int jy = y >> 1, jx = x >> 1;
        int ya, yb, xa, xb; float wya, wyb, wxa, wxb;
        if ((y & 1) == 0) { ya = (jy > 0) ? jy - 1 : 0; yb = jy; wya = 0.25f; wyb = 0.75f; }
        else              { ya = jy; yb = (jy + 1 < Hin) ? jy + 1 : Hin - 1; wya = 0.75f; wyb = 0.25f; }
        if ((x & 1) == 0) { xa = (jx > 0) ? jx - 1 : 0; xb = jx; wxa = 0.25f; wxb = 0.75f; }
        else              { xa = jx; xb = (jx + 1 < Win) ? jx + 1 : Win - 1; wxa = 0.75f; wxb = 0.25f; }
        const float* base = in + (long)bc * Hin * Win * TT;
        p[0] = base + ((long)ya * Win + xa) * TT; w00 = wya * wxa;
        p[1] = base + ((long)ya * Win + xb) * TT; w01 = wya * wxb;
        p[2] = base + ((long)yb * Win + xa) * TT; w10 = wyb * wxa;
        p[3] = base + ((long)yb * Win + xb) * TT; w11 = wyb * wxb;
    } else {
        p[0] = in + (long)n * TT;
    }

    float* ob = out + (long)n * TT;

    float g1 = 0.f, g2 = 0.f, r = 0.f;

    float4 A[S][F4], B[S][F4];

    auto load = [&](float4 (&buf)[S][F4], int c) {
        #pragma unroll
        for (int s = 0; s < S; s++)
            #pragma unroll
            for (int f = 0; f < F4; f++)
                buf[s][f] = *(const float4*)(p[s] + c * CH + f * 4);
    };

    auto compute = [&](float4 (&buf)[S][F4], int c) {
        #pragma unroll
        for (int f = 0; f < F4; f++) {
            float u[4];
            if (MODE == 2) {
                float4 a = buf[0][f], b = buf[1][f], cc = buf[2][f], d = buf[3][f];
                u[0] = 2.75f * ((a.x + b.x) + (cc.x + d.x));
                u[1] = 2.75f * ((a.y + b.y) + (cc.y + d.y));
                u[2] = 2.75f * ((a.z + b.z) + (cc.z + d.z));
                u[3] = 2.75f * ((a.w + b.w) + (cc.w + d.w));
            } else if (MODE == 3) {
                float4 a = buf[0][f], b = buf[1][f], cc = buf[2][f], d = buf[3][f];
                u[0] = w00 * a.x + w01 * b.x + w10 * cc.x + w11 * d.x;
                u[1] = w00 * a.y + w01 * b.y + w10 * cc.y + w11 * d.y;
                u[2] = w00 * a.z + w01 * b.z + w10 * cc.z + w11 * d.z;
                u[3] = w00 * a.w + w01 * b.w + w10 * cc.w + w11 * d.w;
            } else {
                float4 a = buf[0][f];
                u[0] = a.x; u[1] = a.y; u[2] = a.z; u[3] = a.w;
            }
            float o[4];
            #pragma unroll
            for (int j = 0; j < 4; j++) {
                if (MODE == 0) {
                    g1 = fmaf(dsr, g1, u[j]);
                    g2 = fmaf(dsr, g2, g1);
                    o[j] = psc * (g2 - g1);
                } else {
                    float v = u[j] + r - 10.0f;
                    float s = (v >= 0.f) ? 1.f : 0.f;
                    r = dref * (r - 20.f * s);
                    g1 = fmaf(dsr, g1, s);
                    g2 = fmaf(dsr, g2, g1);
                    o[j] = psc * (g2 - g1);
                }
            }
            *(float4*)(ob + c * CH + f * 4) = make_float4(o[0], o[1], o[2], o[3]);
        }
    };

    load(A, 0);
    for (int c = 0; c < NC; c += 2) {
        load(B, c + 1);
        compute(A, c);
        if (c + 2 < NC) load(A, c + 2);
        compute(B, c + 1);
    }
}

// ---------------------------------------------------------------------------
// Fused conv + spike/psp epilogue. 64 threads = one output pixel; each thread
// owns 4 timesteps (float4 = 2 packed u64), OCG output channels.
// Weight table (pre-duplicated f32x2 pairs) and the activation staging buffer
// are UNIONED in one shared allocation: weights are dead once the mainloop
// finishes, so the epilogue reuses the space. This is the occupancy lever:
// smem/block = max(sw, sa) instead of sum.
// EPI = 1: spike + psp.  EPI = 4: spike only (final layer).
// ---------------------------------------------------------------------------
template<int IC, int KS, int PAD, int OCG, int EPI>
__global__ __launch_bounds__(64)
void conv_kernel(const float* __restrict__ in, const float* __restrict__ wgt,
                 float* __restrict__ out, int H, int W, int OC)
{
    constexpr int SW_BYTES = IC * KS * KS * OCG * 8;
    constexpr int SA_BYTES = OCG * 260 * 4;
    constexpr int SM_BYTES = SW_BYTES > SA_BYTES ? SW_BYTES : SA_BYTES;
    __shared__ __align__(16) unsigned char smem_raw[SM_BYTES];
    unsigned long long* sw = (unsigned long long*)smem_raw;
    float (*sa)[260] = (float(*)[260])smem_raw;

    int pix = blockIdx.x;
    int x = pix % W, y = (pix / W) % H, b = pix / (W * H);
    int oc0 = blockIdx.y * OCG;

    for (int i = threadIdx.x; i < IC * KS * KS * OCG; i += 64) {
        int k = i / OCG, o = i % OCG;
        unsigned u = __float_as_uint(wgt[(long)(oc0 + o) * IC * KS * KS + k]);
        sw[i] = ((unsigned long long)u << 32) | u;
    }
    __syncthreads();

    int t = threadIdx.x * 4;
    unsigned long long acc[OCG][2];
    #pragma unroll
    for (int o = 0; o < OCG; o++) { acc[o][0] = 0ull; acc[o][1] = 0ull; }

    const long planeT = (long)H * W * TT;
    const float* inb = in + (long)b * IC * planeT + t;

    #pragma unroll
    for (int kh = 0; kh < KS; kh++) {
        int yy = y + kh - PAD;
        if (yy < 0 || yy >= H) continue;
        #pragma unroll
        for (int kw = 0; kw < KS; kw++) {
            int xx = x + kw - PAD;
            if (xx < 0 || xx >= W) continue;
            const float* p = inb + ((long)yy * W + xx) * TT;
            int kidx = kh * KS + kw;
            #pragma unroll 4
            for (int ic = 0; ic < IC; ic++) {
                ulonglong2 v = *(const ulonglong2*)(p + (long)ic * planeT);
                const unsigned long long* swp = &sw[(ic * KS * KS + kidx) * OCG];
                if constexpr (OCG % 2 == 0) {
                    #pragma unroll
                    for (int o = 0; o < OCG; o += 2) {
                        ulonglong2 wv = *(const ulonglong2*)(swp + o);
                        ffma2(acc[o    ][0], wv.x, v.x);
                        ffma2(acc[o    ][1], wv.x, v.y);
                        ffma2(acc[o + 1][0], wv.y, v.x);
                        ffma2(acc[o + 1][1], wv.y, v.y);
                    }
                } else {
                    #pragma unroll
                    for (int o = 0; o < OCG; o++) {
                        unsigned long long wv = swp[o];
                        ffma2(acc[o][0], wv, v.x);
                        ffma2(acc[o][1], wv, v.y);
                    }
                }
            }
        }
    }

    // All threads done reading sw -> safe to overwrite with sa.
    __syncthreads();

    #pragma unroll
    for (int o = 0; o < OCG; o++) {
        *(float2*)&sa[o][t]     = *(float2*)&acc[o][0];
        *(float2*)&sa[o][t + 2] = *(float2*)&acc[o][1];
    }
    __syncthreads();

    // Per-channel serial recurrence over T (OCG threads; overlapped by the
    // conv mainloops of co-resident blocks).
    if (threadIdx.x < OCG) {
        const float dsr  = 0.9048374180359595f;
        const float psc  = 0.27182818284590452f;
        const float dref = 0.36787944117144233f;
        int oc = threadIdx.x;
        float g1 = 0.f, g2 = 0.f, r = 0.f;
        float4 nxt = *(float4*)&sa[oc][0];
        for (int tt = 0; tt < TT; tt += 4) {
            float4 a = nxt;
            if (tt + 4 < TT) nxt = *(float4*)&sa[oc][tt + 4];
            float u[4] = {a.x, a.y, a.z, a.w};
            float o4[4];
            #pragma unroll
            for (int j = 0; j < 4; j++) {
                float v = u[j] + r - 10.0f;
                float s = (v >= 0.f) ? 1.f : 0.f;
                r = dref * (r - 20.f * s);
                if (EPI == 4) {
                    o4[j] = s;
                } else {
                    g1 = fmaf(dsr, g1, s);
                    g2 = fmaf(dsr, g2, g1);
                    o4[j] = psc * (g2 - g1);
                }
            }
            *(float4*)&sa[oc][tt] = make_float4(o4[0], o4[1], o4[2], o4[3]);
        }
    }
    __syncthreads();

    // Coalesced float4 store of the PSP (or spike) tensor.
    float* ob = out + ((long)b * OC + oc0) * planeT + ((long)y * W + x) * TT + t;
    #pragma unroll
    for (int o = 0; o < OCG; o++)
        *(float4*)(ob + (long)o * planeT) = *(float4*)&sa[o][t];
}

// ---------------------------------------------------------------------------
// 10 launches, ping-pong X<->Y.
// ---------------------------------------------------------------------------
extern "C" void kernel_launch(void* const* d_in, const int* in_sizes, int n_in,
                              void* d_out, int out_size)
{
    const float* inp = (const float*)d_in[0];  // [4,1,32,32,256]
    const float* w1  = (const float*)d_in[1];  // [16,1,5,5,1]
    const float* w2  = (const float*)d_in[2];  // [32,16,3,3,1]
    const float* w3  = (const float*)d_in[3];  // [64,32,3,3,1]
    const float* w4  = (const float*)d_in[4];  // [32,64,3,3,1]
    const float* wo  = (const float*)d_in[5];  // [1,32,1,1,1]
    float* out = (float*)d_out;

    float *X, *Y;
    cudaGetSymbolAddress((void**)&X, g_bufX);
    cudaGetSymbolAddress((void**)&Y, g_bufY);

    // P0 = psp(input) -> X        (N=4096)
    dyn_kernel<0><<<128, 32>>>(inp, X, 32, 32, 4096);

    // P1 = spike/psp(conv1(P0)) -> Y      OCG=8, smem 8.3KB
    conv_kernel<1, 5, 2, 8, 1><<<dim3(4096, 2), 64>>>(X, w1, Y, 32, 32, 16);

    // P2 = pool+spike+psp(P1) -> X   [4,16,16,16]
    dyn_kernel<2><<<256, 64>>>(Y, X, 16, 16, 16384);

    // P3 = spike/psp(conv2(P2)) -> Y      OCG=8, smem 9.2KB
    conv_kernel<16, 3, 1, 8, 1><<<dim3(1024, 4), 64>>>(X, w2, Y, 16, 16, 32);

    // P4 = pool+spike+psp(P3) -> X   [4,32,8,8]
    dyn_kernel<2><<<256, 32>>>(Y, X, 8, 8, 8192);

    // P5 = spike/psp(conv3(P4)) -> Y      OCG=8, smem 18.4KB
    conv_kernel<32, 3, 1, 8, 1><<<dim3(256, 8), 64>>>(X, w3, Y, 8, 8, 64);

    // P6 = up+spike+psp(P5) -> X   [4,64,16,16]
    dyn_kernel<3><<<512, 128>>>(Y, X, 16, 16, 65536);

    // P7 = spike/psp(conv4(P6)) -> Y      OCG=4, smem 18.4KB
    conv_kernel<64, 3, 1, 4, 1><<<dim3(1024, 8), 64>>>(X, w4, Y, 16, 16, 32);

    // P8 = up+spike+psp(P7) -> X   [4,32,32,32]
    dyn_kernel<3><<<1024, 128>>>(Y, X, 32, 32, 131072);

    // out = spike(conv_out(P8))
    conv_kernel<32, 1, 0, 1, 4><<<dim3(4096, 1), 64>>>(X, wo, out, 32, 32, 1);
}